// round 1
// baseline (speedup 1.0000x reference)
#include <cuda_runtime.h>
#include <cstdint>

#define NN 16384
#define DD 8
#define SS 8192
#define TI 32          // i-rows per block (16 packed pairs)
#define TJ 256         // j-cols per block (= blockDim.x)

// -------- scratch (no allocations allowed) --------
__device__ int    g_hist[NN];
__device__ int    g_cols[SS];        // sorted sample_idx values
__device__ float  g_z[SS * DD];      // gathered z in sorted order
__device__ float  g_sq[SS];          // |z|^2 in sorted order
__device__ double g_acc;

// -------- packed f32x2 helpers --------
__device__ __forceinline__ unsigned long long pk2(float lo, float hi) {
    unsigned long long r;
    asm("mov.b64 %0, {%1, %2};" : "=l"(r) : "f"(lo), "f"(hi));
    return r;
}
__device__ __forceinline__ void upk2(unsigned long long v, float& lo, float& hi) {
    asm("mov.b64 {%0, %1}, %2;" : "=f"(lo), "=f"(hi) : "l"(v));
}
__device__ __forceinline__ unsigned long long fma2(unsigned long long a,
                                                   unsigned long long b,
                                                   unsigned long long c) {
    unsigned long long d;
    asm("fma.rn.f32x2 %0, %1, %2, %3;" : "=l"(d) : "l"(a), "l"(b), "l"(c));
    return d;
}
__device__ __forceinline__ unsigned long long add2(unsigned long long a,
                                                   unsigned long long b) {
    unsigned long long d;
    asm("add.rn.f32x2 %0, %1, %2;" : "=l"(d) : "l"(a), "l"(b));
    return d;
}
__device__ __forceinline__ float fsqrt_ap(float x) {
    float r; asm("sqrt.approx.f32 %0, %1;" : "=f"(r) : "f"(x)); return r;
}
__device__ __forceinline__ float frcp_ap(float x) {
    float r; asm("rcp.approx.f32 %0, %1;" : "=f"(r) : "f"(x)); return r;
}

// -------- 1) zero hist + acc --------
__global__ void k_init() {
    int t = blockIdx.x * blockDim.x + threadIdx.x;
    if (t < NN) g_hist[t] = 0;
    if (t == 0) g_acc = 0.0;
}

// -------- 2) histogram of sample_idx --------
__global__ void k_hist(const int* __restrict__ idx) {
    int t = blockIdx.x * blockDim.x + threadIdx.x;
    if (t < SS) atomicAdd(&g_hist[idx[t]], 1);
}

// -------- 3) prefix scan + emit sorted values (counting sort) --------
__global__ void k_scan_emit() {
    __shared__ int sums[512];
    int tid  = threadIdx.x;          // 512 threads, 32 bins each
    int base = tid * 32;
    int s = 0;
#pragma unroll
    for (int k = 0; k < 32; k++) s += g_hist[base + k];
    sums[tid] = s;
    __syncthreads();
    // Hillis-Steele inclusive scan
    for (int off = 1; off < 512; off <<= 1) {
        int v = (tid >= off) ? sums[tid - off] : 0;
        __syncthreads();
        sums[tid] += v;
        __syncthreads();
    }
    int st = (tid > 0) ? sums[tid - 1] : 0;   // exclusive start
    for (int k = 0; k < 32; k++) {
        int b = base + k;
        int c = g_hist[b];
        for (int r = 0; r < c; r++) g_cols[st + r] = b;
        st += c;
    }
}

// -------- 4) gather z, |z|^2 in sorted order --------
__global__ void k_gather(const float* __restrict__ latent) {
    int t = blockIdx.x * blockDim.x + threadIdx.x;
    if (t >= SS) return;
    int v = g_cols[t];
    float4 a = *reinterpret_cast<const float4*>(latent + (size_t)v * DD);
    float4 b = *reinterpret_cast<const float4*>(latent + (size_t)v * DD + 4);
    float sq = a.x * a.x + a.y * a.y + a.z * a.z + a.w * a.w
             + b.x * b.x + b.y * b.y + b.z * b.z + b.w * b.w;
    *reinterpret_cast<float4*>(g_z + (size_t)t * DD)     = a;
    *reinterpret_cast<float4*>(g_z + (size_t)t * DD + 4) = b;
    g_sq[t] = sq;
}

// -------- 5) main: tile TI rows x TJ cols --------
__global__ void __launch_bounds__(TJ) k_main(const float* __restrict__ rel) {
    // zi4[p]: dims interleaved as (zi0[d], zi1[d]) float2 pairs, 16B-aligned
    __shared__ float4 zi4[TI / 2][DD / 2];          // 1024 B
    __shared__ float2 sqi[TI / 2];                  // 128 B
    __shared__ int    srow[TI];                     // 128 B
    __shared__ float  red[8];

    const int tid   = threadIdx.x;
    const int iBase = blockIdx.y * TI;
    const int jBase = blockIdx.x * TJ;

    if (tid < 128) {                  // fill packed z_i pairs
        int p = tid >> 3, d = tid & 7;
        int i0 = iBase + 2 * p;
        float2 pr = make_float2(g_z[(size_t)i0 * DD + d],
                                g_z[(size_t)(i0 + 1) * DD + d]);
        reinterpret_cast<float2*>(zi4)[p * DD + d] = pr;
    } else if (tid < 160) {
        int k = tid - 128;
        srow[k] = g_cols[iBase + k];
    } else if (tid < 176) {
        int p = tid - 160;
        sqi[p] = make_float2(g_sq[iBase + 2 * p], g_sq[iBase + 2 * p + 1]);
    }
    __syncthreads();

    const int j   = jBase + tid;
    const int col = g_cols[j];
    float4 zj0 = *reinterpret_cast<const float4*>(g_z + (size_t)j * DD);
    float4 zj1 = *reinterpret_cast<const float4*>(g_z + (size_t)j * DD + 4);
    const float sqj = g_sq[j];

    // pack (-2*zj_d, -2*zj_d) so d2 = (sqi+sqj) + sum zi_d * (-2 zj_d)
    unsigned long long zm[8];
    zm[0] = pk2(-2.f * zj0.x, -2.f * zj0.x);
    zm[1] = pk2(-2.f * zj0.y, -2.f * zj0.y);
    zm[2] = pk2(-2.f * zj0.z, -2.f * zj0.z);
    zm[3] = pk2(-2.f * zj0.w, -2.f * zj0.w);
    zm[4] = pk2(-2.f * zj1.x, -2.f * zj1.x);
    zm[5] = pk2(-2.f * zj1.y, -2.f * zj1.y);
    zm[6] = pk2(-2.f * zj1.z, -2.f * zj1.z);
    zm[7] = pk2(-2.f * zj1.w, -2.f * zj1.w);
    const unsigned long long sqj2 = pk2(sqj, sqj);

    float acc = 0.f;
#pragma unroll
    for (int p = 0; p < TI / 2; p++) {
        const ulonglong2* zp = reinterpret_cast<const ulonglong2*>(&zi4[p][0]);
        ulonglong2 e0 = zp[0];   // dims 0,1 (pairs over i0,i1)
        ulonglong2 e1 = zp[1];   // dims 2,3
        const ulonglong2* zq = zp + 2;
        ulonglong2 e2 = zq[0];   // dims 4,5  (zi4[p] is 64 B: 4 x ull2 view)
        // note: zi4[p] holds 8 float2 = 4 ulonglong2
        ulonglong2 e3 = zq[1];   // dims 6,7

        unsigned long long d2 = add2(*reinterpret_cast<const unsigned long long*>(&sqi[p]), sqj2);
        d2 = fma2(e0.x, zm[0], d2);
        d2 = fma2(e0.y, zm[1], d2);
        d2 = fma2(e1.x, zm[2], d2);
        d2 = fma2(e1.y, zm[3], d2);
        d2 = fma2(e2.x, zm[4], d2);
        d2 = fma2(e2.y, zm[5], d2);
        d2 = fma2(e3.x, zm[6], d2);
        d2 = fma2(e3.y, zm[7], d2);

        float d2a, d2b;
        upk2(d2, d2a, d2b);

        int i0 = iBase + 2 * p;
        // lane 0
        {
            const float r = __ldg(rel + ((size_t)srow[2 * p] << 14) + col);
            float dv = fsqrt_ap(fmaxf(d2a, 0.f));
            float t  = dv - r;
            float den = (i0 == j) ? 5.0f : r;
            acc = fmaf(t * t, frcp_ap(den), acc);
        }
        // lane 1
        {
            const float r = __ldg(rel + ((size_t)srow[2 * p + 1] << 14) + col);
            float dv = fsqrt_ap(fmaxf(d2b, 0.f));
            float t  = dv - r;
            float den = ((i0 + 1) == j) ? 5.0f : r;
            acc = fmaf(t * t, frcp_ap(den), acc);
        }
    }

    // block reduction
#pragma unroll
    for (int o = 16; o > 0; o >>= 1)
        acc += __shfl_down_sync(0xFFFFFFFFu, acc, o);
    if ((tid & 31) == 0) red[tid >> 5] = acc;
    __syncthreads();
    if (tid < 8) {
        float v = red[tid];
#pragma unroll
        for (int o = 4; o > 0; o >>= 1)
            v += __shfl_down_sync(0xFFu, v, o);
        if (tid == 0) atomicAdd(&g_acc, (double)v);
    }
}

// -------- 6) finalize --------
__global__ void k_final(float* __restrict__ out) {
    out[0] = (float)sqrt(g_acc);
}

extern "C" void kernel_launch(void* const* d_in, const int* in_sizes, int n_in,
                              void* d_out, int out_size) {
    const float* latent = (const float*)d_in[0];   // [N, D] fp32
    const float* relmat = (const float*)d_in[1];   // [N, N] fp32
    const int*   sidx   = (const int*)d_in[2];     // [S]   int32
    float* out = (float*)d_out;
    (void)in_sizes; (void)n_in; (void)out_size;

    k_init<<<NN / 256, 256>>>();
    k_hist<<<SS / 256, 256>>>(sidx);
    k_scan_emit<<<1, 512>>>();
    k_gather<<<SS / 256, 256>>>(latent);

    dim3 grid(SS / TJ, SS / TI);   // (32 j-tiles, 256 i-tiles)
    k_main<<<grid, TJ>>>(relmat);

    k_final<<<1, 1>>>(out);
}